// round 1
// baseline (speedup 1.0000x reference)
#include <cuda_runtime.h>
#include <math.h>

// Problem constants
#define B_    4
#define L_    2048
#define DM_   1024
#define NL_   2
#define ED_   2048
#define N_    2
#define DTR_  64
#define SEG_  256
#define NSEG_ 8
#define BL_   (B_*L_)      // 8192
#define MSEG_ (B_*SEG_)    // 1024
#define T3_   (3*ED_)      // 6144
#define DCN_  (DTR_+N_)    // 66

#define ACT_NONE 0
#define ACT_RELU 1
#define ACT_SP   2

// ---------------- scratch (static device globals; no allocation) ----------------
__device__ float g_xn   [(size_t)BL_*DM_];
__device__ float g_xz   [(size_t)BL_*2*ED_];
__device__ float g_xs   [(size_t)BL_*ED_];
__device__ float g_delta[(size_t)BL_*ED_];
__device__ float g_dC   [(size_t)BL_*DCN_];
__device__ float g_y    [(size_t)BL_*ED_];
__device__ float g_gated[(size_t)BL_*ED_];
__device__ float g_Kerr [(size_t)MSEG_*ED_];
__device__ float g_K    [(size_t)MSEG_*ED_];
__device__ float g_h1   [(size_t)MSEG_*T3_];
__device__ float g_h2   [(size_t)MSEG_*ED_];
__device__ float g_h3   [(size_t)MSEG_*ED_];
__device__ float g_Xr   [(size_t)MSEG_*ED_];
__device__ float g_Xi   [(size_t)MSEG_*ED_];
__device__ float g_Kdy  [(size_t)MSEG_*ED_];

// ---------------- helpers ----------------
__device__ __forceinline__ float siluf(float v) { return v / (1.f + expf(-v)); }

// ---------------- RMSNorm ----------------
__global__ void rmsnorm_kernel(const float* __restrict__ h, const float* __restrict__ w,
                               float* __restrict__ out) {
    int row = blockIdx.x;
    const float* hr = h + (size_t)row * DM_;
    float v[4];
    float s = 0.f;
#pragma unroll
    for (int i = 0; i < 4; i++) { v[i] = hr[threadIdx.x + i*256]; s += v[i]*v[i]; }
    __shared__ float sh[8];
    int lane = threadIdx.x & 31, wp = threadIdx.x >> 5;
#pragma unroll
    for (int o = 16; o; o >>= 1) s += __shfl_xor_sync(0xffffffffu, s, o);
    if (lane == 0) sh[wp] = s;
    __syncthreads();
    if (wp == 0) {
        float t = (lane < 8) ? sh[lane] : 0.f;
#pragma unroll
        for (int o = 4; o; o >>= 1) t += __shfl_xor_sync(0xffffffffu, t, o);
        if (lane == 0) sh[0] = t;
    }
    __syncthreads();
    float rs = rsqrtf(sh[0] * (1.f/DM_) + 1e-5f);
    float* orow = out + (size_t)row * DM_;
#pragma unroll
    for (int i = 0; i < 4; i++) { int d = threadIdx.x + i*256; orow[d] = v[i]*rs*w[d]; }
}

// ---------------- SGEMM: C(M,N) = act(A(M,K) * B(N,K)^T + bias), optional +=  ----------------
__global__ __launch_bounds__(256)
void sgemm_kernel(const float* __restrict__ A, const float* __restrict__ Bm,
                  float* __restrict__ C, const float* __restrict__ bias,
                  int M, int N, int K, int lda, int ldb, int ldc,
                  int act, int accum) {
    __shared__ float As[16][132];
    __shared__ float Bs[16][132];
    int tid = threadIdx.x;
    int bm = blockIdx.y * 128, bn = blockIdx.x * 128;
    int tx = tid & 15, ty = tid >> 4;
    float acc[8][8];
#pragma unroll
    for (int i = 0; i < 8; i++)
#pragma unroll
        for (int j = 0; j < 8; j++) acc[i][j] = 0.f;

    for (int k0 = 0; k0 < K; k0 += 16) {
#pragma unroll
        for (int i = 0; i < 8; i++) {
            int idx = tid + i*256;
            int r = idx >> 4, c = idx & 15;
            int gk = k0 + c;
            int gm = bm + r;
            As[c][r] = (gm < M && gk < K) ? A[(size_t)gm*lda + gk] : 0.f;
            int gn = bn + r;
            Bs[c][r] = (gn < N && gk < K) ? Bm[(size_t)gn*ldb + gk] : 0.f;
        }
        __syncthreads();
#pragma unroll
        for (int kk = 0; kk < 16; kk++) {
            float a[8], b[8];
#pragma unroll
            for (int i = 0; i < 8; i++) a[i] = As[kk][ty*8 + i];
#pragma unroll
            for (int j = 0; j < 8; j++) b[j] = Bs[kk][tx*8 + j];
#pragma unroll
            for (int i = 0; i < 8; i++)
#pragma unroll
                for (int j = 0; j < 8; j++) acc[i][j] += a[i]*b[j];
        }
        __syncthreads();
    }
#pragma unroll
    for (int i = 0; i < 8; i++) {
        int row = bm + ty*8 + i;
        if (row >= M) continue;
#pragma unroll
        for (int j = 0; j < 8; j++) {
            int col = bn + tx*8 + j;
            if (col >= N) continue;
            float v = acc[i][j];
            if (bias) v += bias[col];
            if (act == ACT_RELU)      v = fmaxf(v, 0.f);
            else if (act == ACT_SP)   v = (v > 20.f) ? v : log1pf(expf(v));
            size_t o = (size_t)row*ldc + col;
            if (accum) C[o] += v; else C[o] = v;
        }
    }
}

// ---------------- fused 2x depthwise conv (k=2, causal) + SiLU ----------------
__global__ void conv_silu_kernel(const float* __restrict__ xz,
                                 const float* __restrict__ c1w, const float* __restrict__ c1b,
                                 const float* __restrict__ c2w, const float* __restrict__ c2b,
                                 float* __restrict__ out) {
    size_t idx = (size_t)blockIdx.x * blockDim.x + threadIdx.x;
    if (idx >= (size_t)BL_*ED_) return;
    int e = (int)(idx % ED_);
    size_t bl = idx / ED_;
    int l = (int)(bl % L_);
    size_t base = bl * (size_t)(2*ED_) + e;
    float x2 = xz[base];
    float x1 = (l >= 1) ? xz[base - 2*ED_] : 0.f;
    float x0 = (l >= 2) ? xz[base - 4*ED_] : 0.f;
    float w10 = c1w[e*2], w11 = c1w[e*2+1], b1 = c1b[e];
    float w20 = c2w[e*2], w21 = c2w[e*2+1], b2 = c2b[e];
    float y1b = b1 + w10*x1 + w11*x2;
    float y1a = (l >= 1) ? (b1 + w10*x0 + w11*x1) : 0.f;  // conv2 input padded with 0
    float y2 = b2 + w20*y1a + w21*y1b;
    out[idx] = siluf(y2);
}

// ---------------- Kerr = softsign((xg - y_prev)^2) ----------------
__global__ void kerr_kernel(const float* __restrict__ xs, const float* __restrict__ y,
                            float* __restrict__ kerr, int s0, int useY) {
    size_t idx = (size_t)blockIdx.x * blockDim.x + threadIdx.x;
    if (idx >= (size_t)MSEG_*ED_) return;
    int e = (int)(idx % ED_);
    int row = (int)(idx / ED_);
    int b = row / SEG_, t = row % SEG_;
    size_t xi = ((size_t)(b*L_ + s0 + t))*ED_ + e;
    float xv = xs[xi];
    float yv = useY ? y[xi - (size_t)SEG_*ED_] : 0.f;
    float u = xv - yv; u = u*u;
    kerr[idx] = u / (1.f + u);
}

// ---------------- LayerNorm(h3) + K EMA update ----------------
__global__ void ln_kupdate_kernel(const float* __restrict__ h3, const float* __restrict__ g,
                                  const float* __restrict__ bb, const float* __restrict__ kalpha,
                                  float* __restrict__ K) {
    int row = blockIdx.x;   // MSEG_
    const float* hr = h3 + (size_t)row * ED_;
    float v[8];
    float s = 0.f;
#pragma unroll
    for (int i = 0; i < 8; i++) { v[i] = hr[threadIdx.x + i*256]; s += v[i]; }
    __shared__ float sh[8];
    __shared__ float mu_s, rs_s;
    int lane = threadIdx.x & 31, wp = threadIdx.x >> 5;
#pragma unroll
    for (int o = 16; o; o >>= 1) s += __shfl_xor_sync(0xffffffffu, s, o);
    if (lane == 0) sh[wp] = s;
    __syncthreads();
    if (threadIdx.x == 0) {
        float t = 0.f;
#pragma unroll
        for (int i = 0; i < 8; i++) t += sh[i];
        mu_s = t * (1.f/ED_);
    }
    __syncthreads();
    float mu = mu_s;
    float s2 = 0.f;
#pragma unroll
    for (int i = 0; i < 8; i++) { float d = v[i] - mu; s2 += d*d; }
#pragma unroll
    for (int o = 16; o; o >>= 1) s2 += __shfl_xor_sync(0xffffffffu, s2, o);
    if (lane == 0) sh[wp] = s2;
    __syncthreads();
    if (threadIdx.x == 0) {
        float t = 0.f;
#pragma unroll
        for (int i = 0; i < 8; i++) t += sh[i];
        rs_s = rsqrtf(t * (1.f/ED_) + 1e-5f);
    }
    __syncthreads();
    float rs = rs_s;
#pragma unroll
    for (int i = 0; i < 8; i++) {
        int e = threadIdx.x + i*256;
        float a = fminf(fmaxf(kalpha[e], 0.01f), 0.99f);
        float kn = g[e]*(v[i] - mu)*rs + bb[e];
        size_t ki = (size_t)row*ED_ + e;
        K[ki] = (1.f - a)*K[ki] + a*kn;
    }
}

// ---------------- DFT forward: X[k] = sum_t x[t] e^{-2pi i k t/T}, 4 signals/block ----------------
__global__ void dft_fwd_kernel(const float* __restrict__ xs, float* __restrict__ Xr,
                               float* __restrict__ Xi, int s0) {
    int blk = blockIdx.x;                 // B*ED/4
    int b = blk / (ED_/4);
    int e0 = (blk % (ED_/4)) * 4;
    __shared__ float xsh[4][SEG_+4];
    __shared__ float ct[SEG_], st[SEG_];
    int t = threadIdx.x;
    {
        float ang = 6.283185307179586f * (float)t / (float)SEG_;
        ct[t] = cosf(ang); st[t] = sinf(ang);
    }
#pragma unroll
    for (int j = 0; j < 4; j++) {
        int idx = t + j*256;
        int q = idx & 3, tt = idx >> 2;
        xsh[q][tt] = xs[((size_t)(b*L_ + s0 + tt))*ED_ + e0 + q];
    }
    __syncthreads();
    float ar[4] = {0,0,0,0}, ai[4] = {0,0,0,0};
    int k = t;
    for (int tt = 0; tt < SEG_; tt++) {
        int p = (k*tt) & (SEG_-1);
        float c = ct[p], s = st[p];
#pragma unroll
        for (int q = 0; q < 4; q++) { float xv = xsh[q][tt]; ar[q] += xv*c; ai[q] -= xv*s; }
    }
#pragma unroll
    for (int q = 0; q < 4; q++) {
        size_t o = ((size_t)(b*ED_ + e0 + q))*SEG_ + k;
        Xr[o] = ar[q]; Xi[o] = ai[q];
    }
}

// ---------------- inverse DFT of i*omega*g*X, then Kdy = K * real(ifft) ----------------
__global__ void dft_inv_kernel(const float* __restrict__ Xr, const float* __restrict__ Xi,
                               const float* __restrict__ delta, const float* __restrict__ Kbuf,
                               const float* __restrict__ sigp, float* __restrict__ Kdy, int s0) {
    int blk = blockIdx.x;
    int b = blk / (ED_/4);
    int e0 = (blk % (ED_/4)) * 4;
    float sig = *sigp;
    __shared__ float Yr[4][SEG_+4], Yi[4][SEG_+4];
    __shared__ float ct[SEG_], st[SEG_];
    int t = threadIdx.x;
    {
        float ang = 6.283185307179586f * (float)t / (float)SEG_;
        ct[t] = cosf(ang); st[t] = sinf(ang);
    }
    {
        int k = t;
        float f = (k < SEG_/2) ? (float)k/(float)SEG_ : (float)(k - SEG_)/(float)SEG_;
        float g = expf(-f*f*sig*sig);
        float wbase = 6.283185307179586f * f;
#pragma unroll
        for (int q = 0; q < 4; q++) {
            float dt = delta[((size_t)(b*L_ + s0 + k))*ED_ + e0 + q];
            float w = wbase / (dt + 1e-5f);
            size_t o = ((size_t)(b*ED_ + e0 + q))*SEG_ + k;
            float xr = Xr[o], xi = Xi[o];
            Yr[q][k] = -w*g*xi;
            Yi[q][k] =  w*g*xr;
        }
    }
    __syncthreads();
    float acc[4] = {0,0,0,0};
    for (int k = 0; k < SEG_; k++) {
        int p = (k*t) & (SEG_-1);
        float c = ct[p], s = st[p];
#pragma unroll
        for (int q = 0; q < 4; q++) acc[q] += Yr[q][k]*c - Yi[q][k]*s;
    }
#pragma unroll
    for (int q = 0; q < 4; q++) {
        size_t oi = ((size_t)(b*SEG_ + t))*ED_ + e0 + q;
        Kdy[oi] = Kbuf[oi] * acc[q] * (1.f/(float)SEG_);
    }
}

// ---------------- segment scan: chunked two-pass, writes y directly ----------------
__global__ void scan_kernel(const float* __restrict__ xs, const float* __restrict__ delta,
                            const float* __restrict__ Kbuf, const float* __restrict__ Kdy,
                            const float* __restrict__ dC, const float* __restrict__ Alog,
                            const float* __restrict__ Dp, float* __restrict__ y, int s0) {
    int b = blockIdx.y;
    int lane = threadIdx.x & 31;
    int chunk = threadIdx.x >> 5;           // 0..7
    int e = blockIdx.x*32 + lane;
    __shared__ float C0s[SEG_], C1s[SEG_];
    __shared__ float sA0[8][33], sB0[8][33], sA1[8][33], sB1[8][33];
    __shared__ float pB0[8][33], pB1[8][33];
    {
        int t = threadIdx.x;
        size_t ci = ((size_t)(b*L_ + s0 + t))*DCN_ + DTR_;
        C0s[t] = dC[ci];
        C1s[t] = dC[ci + 1];
    }
    float A0v = -expf(Alog[e*2]);
    float A1v = -expf(Alog[e*2 + 1]);
    float Dpe = Dp[e];
    __syncthreads();

    // pass 1: chunk aggregates
    float Ag0 = 1.f, Bg0 = 0.f, Ag1 = 1.f, Bg1 = 0.f;
    int tbase = chunk*32;
    for (int j = 0; j < 32; j++) {
        int t = tbase + j;
        size_t xi = ((size_t)(b*L_ + s0 + t))*ED_ + e;
        size_t ki = ((size_t)(b*SEG_ + t))*ED_ + e;
        float x = xs[xi], dg = delta[xi], Kv = Kbuf[ki], kd = Kdy[ki];
        float C0 = C0s[t], C1 = C1s[t];
        float KC0 = Kv*C0, AmK0 = A0v*(1.f - KC0);
        float a0 = expf(dg*AmK0*(1.f + KC0));
        float b0 = -dg*AmK0*Kv*x + kd;
        Bg0 = a0*Bg0 + b0; Ag0 *= a0;
        float KC1 = Kv*C1, AmK1 = A1v*(1.f - KC1);
        float a1 = expf(dg*AmK1*(1.f + KC1));
        float b1 = -dg*AmK1*Kv*x + kd;
        Bg1 = a1*Bg1 + b1; Ag1 *= a1;
    }
    sA0[chunk][lane] = Ag0; sB0[chunk][lane] = Bg0;
    sA1[chunk][lane] = Ag1; sB1[chunk][lane] = Bg1;
    __syncthreads();

    // chunk prefix (initial state 0 -> entering state is prefix B)
    if (threadIdx.x < 64) {
        int s = threadIdx.x >> 5, ln = threadIdx.x & 31;
        float pb = 0.f;
        if (s == 0) {
#pragma unroll
            for (int c = 0; c < 8; c++) { pB0[c][ln] = pb; pb = sA0[c][ln]*pb + sB0[c][ln]; }
        } else {
#pragma unroll
            for (int c = 0; c < 8; c++) { pB1[c][ln] = pb; pb = sA1[c][ln]*pb + sB1[c][ln]; }
        }
    }
    __syncthreads();

    // pass 2: replay with entering state, emit y
    float h0 = pB0[chunk][lane], h1 = pB1[chunk][lane];
    for (int j = 0; j < 32; j++) {
        int t = tbase + j;
        size_t xi = ((size_t)(b*L_ + s0 + t))*ED_ + e;
        size_t ki = ((size_t)(b*SEG_ + t))*ED_ + e;
        float x = xs[xi], dg = delta[xi], Kv = Kbuf[ki], kd = Kdy[ki];
        float C0 = C0s[t], C1 = C1s[t];
        float KC0 = Kv*C0, AmK0 = A0v*(1.f - KC0);
        float a0 = expf(dg*AmK0*(1.f + KC0));
        float b0 = -dg*AmK0*Kv*x + kd;
        h0 = a0*h0 + b0;
        float KC1 = Kv*C1, AmK1 = A1v*(1.f - KC1);
        float a1 = expf(dg*AmK1*(1.f + KC1));
        float b1 = -dg*AmK1*Kv*x + kd;
        h1 = a1*h1 + b1;
        y[xi] = h0*C0 + h1*C1 + Dpe*x;
    }
}

// ---------------- gate: gated = y * silu(z) ----------------
__global__ void gate_kernel(const float* __restrict__ y, const float* __restrict__ xz,
                            float* __restrict__ gated) {
    size_t idx = (size_t)blockIdx.x * blockDim.x + threadIdx.x;
    if (idx >= (size_t)BL_*ED_) return;
    int e = (int)(idx % ED_);
    size_t bl = idx / ED_;
    float z = xz[bl*(size_t)(2*ED_) + ED_ + e];
    gated[idx] = y[idx] * siluf(z);
}

// ---------------- host orchestration ----------------
extern "C" void kernel_launch(void* const* d_in, const int* in_sizes, int n_in,
                              void* d_out, int out_size) {
    const float* x      = (const float*)d_in[0];
    const float* rms_w  = (const float*)d_in[1];
    const float* in_w   = (const float*)d_in[2];
    const float* c1_w   = (const float*)d_in[3];
    const float* c1_b   = (const float*)d_in[4];
    const float* c2_w   = (const float*)d_in[5];
    const float* c2_b   = (const float*)d_in[6];
    const float* xp_w   = (const float*)d_in[7];
    const float* dt_w   = (const float*)d_in[8];
    const float* dt_b   = (const float*)d_in[9];
    const float* A_log  = (const float*)d_in[10];
    const float* Dp     = (const float*)d_in[11];
    const float* out_w  = (const float*)d_in[12];
    const float* k1_w   = (const float*)d_in[13];
    const float* k1_b   = (const float*)d_in[14];
    const float* k2_w   = (const float*)d_in[15];
    const float* k3_w   = (const float*)d_in[16];
    const float* ln_g   = (const float*)d_in[17];
    const float* ln_b   = (const float*)d_in[18];
    const float* kalpha = (const float*)d_in[19];
    const float* sigma  = (const float*)d_in[20];

    float* h = (float*)d_out;

    float *xn, *xz, *xs, *delta, *dC, *y, *gated, *Kerr, *K, *h1, *h2, *h3, *Xr, *Xi, *Kdy;
    cudaGetSymbolAddress((void**)&xn,    g_xn);
    cudaGetSymbolAddress((void**)&xz,    g_xz);
    cudaGetSymbolAddress((void**)&xs,    g_xs);
    cudaGetSymbolAddress((void**)&delta, g_delta);
    cudaGetSymbolAddress((void**)&dC,    g_dC);
    cudaGetSymbolAddress((void**)&y,     g_y);
    cudaGetSymbolAddress((void**)&gated, g_gated);
    cudaGetSymbolAddress((void**)&Kerr,  g_Kerr);
    cudaGetSymbolAddress((void**)&K,     g_K);
    cudaGetSymbolAddress((void**)&h1,    g_h1);
    cudaGetSymbolAddress((void**)&h2,    g_h2);
    cudaGetSymbolAddress((void**)&h3,    g_h3);
    cudaGetSymbolAddress((void**)&Xr,    g_Xr);
    cudaGetSymbolAddress((void**)&Xi,    g_Xi);
    cudaGetSymbolAddress((void**)&Kdy,   g_Kdy);

    // h = x (residual stream lives in d_out)
    cudaMemcpyAsync(h, x, sizeof(float)*(size_t)BL_*DM_, cudaMemcpyDeviceToDevice);

    const int EL_BLOCKS = (int)(((size_t)BL_*ED_ + 255) / 256);
    const int KE_BLOCKS = (int)(((size_t)MSEG_*ED_ + 255) / 256);

    for (int i = 0; i < NL_; i++) {
        const float* rw   = rms_w + (size_t)i*DM_;
        const float* iw   = in_w  + (size_t)i*2*ED_*DM_;
        const float* c1wi = c1_w  + (size_t)i*ED_*2;
        const float* c1bi = c1_b  + (size_t)i*ED_;
        const float* c2wi = c2_w  + (size_t)i*ED_*2;
        const float* c2bi = c2_b  + (size_t)i*ED_;
        const float* xpwi = xp_w  + (size_t)i*DCN_*ED_;
        const float* dtwi = dt_w  + (size_t)i*ED_*DTR_;
        const float* dtbi = dt_b  + (size_t)i*ED_;
        const float* Ali  = A_log + (size_t)i*ED_*N_;
        const float* Dpi  = Dp    + (size_t)i*ED_;
        const float* owi  = out_w + (size_t)i*DM_*ED_;
        const float* k1wi = k1_w  + (size_t)i*T3_*ED_;
        const float* k1bi = k1_b  + (size_t)i*T3_;
        const float* k2wi = k2_w  + (size_t)i*ED_*T3_;
        const float* k3wi = k3_w  + (size_t)i*ED_*ED_;
        const float* lngi = ln_g  + (size_t)i*ED_;
        const float* lnbi = ln_b  + (size_t)i*ED_;
        const float* kai  = kalpha+ (size_t)i*ED_;
        const float* sigi = sigma + i;

        // RMSNorm
        rmsnorm_kernel<<<BL_, 256>>>(h, rw, xn);
        // in-proj: xz = xn @ in_w^T   (8192 x 4096 x 1024)
        sgemm_kernel<<<dim3((2*ED_+127)/128, (BL_+127)/128), 256>>>(
            xn, iw, xz, nullptr, BL_, 2*ED_, DM_, DM_, DM_, 2*ED_, ACT_NONE, 0);
        // fused conv1 -> conv2 -> silu
        conv_silu_kernel<<<EL_BLOCKS, 256>>>(xz, c1wi, c1bi, c2wi, c2bi, xs);
        // dC = xs @ xp_w^T (N=66)
        sgemm_kernel<<<dim3((DCN_+127)/128, (BL_+127)/128), 256>>>(
            xs, xpwi, dC, nullptr, BL_, DCN_, ED_, ED_, ED_, DCN_, ACT_NONE, 0);
        // delta = softplus(dr @ dt_w^T + dt_b)  (dr = dC[:, :64], lda=66)
        sgemm_kernel<<<dim3((ED_+127)/128, (BL_+127)/128), 256>>>(
            dC, dtwi, delta, dtbi, BL_, ED_, DTR_, DCN_, DTR_, ED_, ACT_SP, 0);

        // K = 0
        cudaMemsetAsync(K, 0, sizeof(float)*(size_t)MSEG_*ED_);

        for (int s = 0; s < NSEG_; s++) {
            int s0 = s * SEG_;
            kerr_kernel<<<KE_BLOCKS, 256>>>(xs, y, Kerr, s0, s > 0);
            // h1 = relu(Kerr @ k1_w^T + k1_b)   (1024 x 6144 x 2048)
            sgemm_kernel<<<dim3((T3_+127)/128, (MSEG_+127)/128), 256>>>(
                Kerr, k1wi, h1, k1bi, MSEG_, T3_, ED_, ED_, ED_, T3_, ACT_RELU, 0);
            // h2 = relu(h1 @ k2_w^T)            (1024 x 2048 x 6144)
            sgemm_kernel<<<dim3((ED_+127)/128, (MSEG_+127)/128), 256>>>(
                h1, k2wi, h2, nullptr, MSEG_, ED_, T3_, T3_, T3_, ED_, ACT_RELU, 0);
            // h3 = h2 @ k3_w^T                  (1024 x 2048 x 2048)
            sgemm_kernel<<<dim3((ED_+127)/128, (MSEG_+127)/128), 256>>>(
                h2, k3wi, h3, nullptr, MSEG_, ED_, ED_, ED_, ED_, ED_, ACT_NONE, 0);
            // K = (1-a)K + a*LN(h3)
            ln_kupdate_kernel<<<MSEG_, 256>>>(h3, lngi, lnbi, kai, K);
            // FFT derivative unit
            dft_fwd_kernel<<<B_*ED_/4, 256>>>(xs, Xr, Xi, s0);
            dft_inv_kernel<<<B_*ED_/4, 256>>>(Xr, Xi, delta, K, sigi, Kdy, s0);
            // scan -> y segment
            scan_kernel<<<dim3(ED_/32, B_), 256>>>(xs, delta, K, Kdy, dC, Ali, Dpi, y, s0);
        }

        // gated = y * silu(z)
        gate_kernel<<<EL_BLOCKS, 256>>>(y, xz, gated);
        // h += gated @ out_w^T  (8192 x 1024 x 2048)
        sgemm_kernel<<<dim3((DM_+127)/128, (BL_+127)/128), 256>>>(
            gated, owi, h, nullptr, BL_, DM_, ED_, ED_, ED_, DM_, ACT_NONE, 1);
    }
}

// round 3
// speedup vs baseline: 2.4244x; 2.4244x over previous
#include <cuda_runtime.h>
#include <cuda_bf16.h>
#include <math.h>
#include <cstdint>

// Problem constants
#define B_    4
#define L_    2048
#define DM_   1024
#define NL_   2
#define ED_   2048
#define N_    2
#define DTR_  64
#define SEG_  256
#define NSEG_ 8
#define BL_   (B_*L_)      // 8192
#define MSEG_ (B_*SEG_)    // 1024
#define T3_   (3*ED_)      // 6144
#define DCN_  (DTR_+N_)    // 66

#define ACT_NONE 0
#define ACT_RELU 1
#define ACT_SP   2

// ---------------- scratch (static device globals; no allocation) ----------------
__device__ float g_xz   [(size_t)BL_*2*ED_];
__device__ float g_xs   [(size_t)BL_*ED_];
__device__ float g_delta[(size_t)BL_*ED_];
__device__ float g_dC   [(size_t)BL_*DCN_];
__device__ float g_y    [(size_t)BL_*ED_];
__device__ float g_K    [(size_t)MSEG_*ED_];
__device__ float g_h3   [(size_t)MSEG_*ED_];
__device__ float g_Xr   [(size_t)MSEG_*ED_];
__device__ float g_Xi   [(size_t)MSEG_*ED_];
__device__ float g_Kdy  [(size_t)MSEG_*ED_];
// bf16x3 buffers (A-side: [hi|lo|hi], B-side: [hi|hi|lo])
__device__ __nv_bfloat16 g_xn3   [(size_t)BL_*3*DM_];
__device__ __nv_bfloat16 g_inw3  [(size_t)2*ED_*3*DM_];
__device__ __nv_bfloat16 g_kerr3 [(size_t)MSEG_*3*ED_];
__device__ __nv_bfloat16 g_k1w3  [(size_t)T3_*3*ED_];
__device__ __nv_bfloat16 g_h13   [(size_t)MSEG_*3*T3_];
__device__ __nv_bfloat16 g_k2w3  [(size_t)ED_*3*T3_];
__device__ __nv_bfloat16 g_h23   [(size_t)MSEG_*3*ED_];
__device__ __nv_bfloat16 g_k3w3  [(size_t)ED_*3*ED_];
__device__ __nv_bfloat16 g_gt3   [(size_t)BL_*3*ED_];
__device__ __nv_bfloat16 g_outw3 [(size_t)DM_*3*ED_];

__device__ __forceinline__ uint32_t smem_to_u32(const void* p) {
    uint32_t a;
    asm("{ .reg .u64 t; cvta.to.shared.u64 t, %1; cvt.u32.u64 %0, t; }" : "=r"(a) : "l"(p));
    return a;
}
__device__ __forceinline__ float siluf(float v) { return v / (1.f + expf(-v)); }

#define CP16(dst, src) \
    asm volatile("cp.async.cg.shared.global [%0], [%1], 16;" :: "r"(dst), "l"(src))
#define CP_COMMIT() asm volatile("cp.async.commit_group;")
#define CP_WAIT2()  asm volatile("cp.async.wait_group 2;")

__device__ __forceinline__ void ldmx4(uint32_t* r, uint32_t addr) {
    asm volatile("ldmatrix.sync.aligned.m8n8.x4.shared.b16 {%0,%1,%2,%3}, [%4];"
        : "=r"(r[0]), "=r"(r[1]), "=r"(r[2]), "=r"(r[3]) : "r"(addr));
}
__device__ __forceinline__ void mma_bf16(float* d, const uint32_t* a, const uint32_t* b) {
    asm volatile("mma.sync.aligned.m16n8k16.row.col.f32.bf16.bf16.f32 "
        "{%0,%1,%2,%3}, {%4,%5,%6,%7}, {%8,%9}, {%0,%1,%2,%3};"
        : "+f"(d[0]), "+f"(d[1]), "+f"(d[2]), "+f"(d[3])
        : "r"(a[0]), "r"(a[1]), "r"(a[2]), "r"(a[3]), "r"(b[0]), "r"(b[1]));
}

// ================= bf16 mma.sync GEMM: D(M,N) = A3(M,K3) * B3(N,K3)^T =================
// 128x128 CTA tile, BK=32, 4-stage cp.async, 8 warps (2x4), 64x32 warp tile.
#define ROWB   80                 // 32 bf16 (64B) + 16B pad per row
#define STG_A  (128*ROWB)         // 10240
#define STG    (2*STG_A)          // 20480 per stage
#define NST    4
#define TCG_SMEM (NST*STG)        // 81920

__global__ __launch_bounds__(256, 2)
void tcgemm_kernel(const __nv_bfloat16* __restrict__ A3, const __nv_bfloat16* __restrict__ B3,
                   float* __restrict__ Cf, __nv_bfloat16* __restrict__ Ct,
                   const float* __restrict__ bias,
                   int K3, int ldc, int Kn, int act, int accum)
{
    extern __shared__ __align__(128) char sm[];
    const uint32_t sbase = smem_to_u32(sm);
    const int tid = threadIdx.x, lane = tid & 31, wid = tid >> 5;
    const int wm = wid & 1, wn = wid >> 1;        // 2 x 4 warp grid
    const int bm = blockIdx.y * 128, bn = blockIdx.x * 128;
    const __nv_bfloat16* Arow = A3 + (size_t)bm * K3;
    const __nv_bfloat16* Brow = B3 + (size_t)bn * K3;

    // per-lane ldmatrix byte offsets within a stage
    uint32_t a_off[4], b_off[2];
#pragma unroll
    for (int mi = 0; mi < 4; mi++) {
        int row = wm*64 + mi*16 + (lane & 15);
        a_off[mi] = row*ROWB + (lane >> 4) * 16;
    }
#pragma unroll
    for (int nt = 0; nt < 2; nt++) {
        int row = wn*32 + nt*16 + (lane & 7) + ((lane >> 4) * 8);
        b_off[nt] = STG_A + row*ROWB + ((lane >> 3) & 1) * 16;
    }

    const int nchunk = K3 / 32;

    auto issue = [&](int c) {
        uint32_t base = sbase + (c & 3) * STG;
        size_t k0 = (size_t)c * 32;
#pragma unroll
        for (int i = 0; i < 2; i++) {
            int idx = tid + i*256;              // 0..511
            int row = idx >> 2, ch = idx & 3;
            CP16(base + row*ROWB + ch*16,         (const void*)(Arow + (size_t)row*K3 + k0 + ch*8));
            CP16(base + STG_A + row*ROWB + ch*16, (const void*)(Brow + (size_t)row*K3 + k0 + ch*8));
        }
    };

    float acc[4][4][4];
#pragma unroll
    for (int i = 0; i < 4; i++)
#pragma unroll
        for (int j = 0; j < 4; j++)
#pragma unroll
            for (int q = 0; q < 4; q++) acc[i][j][q] = 0.f;

    issue(0); CP_COMMIT();
    issue(1); CP_COMMIT();
    issue(2); CP_COMMIT();

    for (int c = 0; c < nchunk; c++) {
        CP_WAIT2();
        __syncthreads();
        uint32_t base = sbase + (c & 3) * STG;
#pragma unroll
        for (int kk = 0; kk < 2; kk++) {        // two k16 steps (byte offset 0 / 32)
            uint32_t a[4][4], b[2][4];
#pragma unroll
            for (int mi = 0; mi < 4; mi++) ldmx4(a[mi], base + a_off[mi] + kk*32);
#pragma unroll
            for (int nt = 0; nt < 2; nt++) ldmx4(b[nt], base + b_off[nt] + kk*32);
#pragma unroll
            for (int mi = 0; mi < 4; mi++)
#pragma unroll
                for (int ni = 0; ni < 4; ni++)
                    mma_bf16(acc[mi][ni], a[mi], &b[ni >> 1][(ni & 1) * 2]);
        }
        __syncthreads();
        if (c + 3 < nchunk) issue(c + 3);
        CP_COMMIT();   // exactly one group per iteration (may be empty)
    }

    // ---- epilogue ----
#pragma unroll
    for (int mi = 0; mi < 4; mi++) {
        int r0 = bm + wm*64 + mi*16 + (lane >> 2);
#pragma unroll
        for (int half = 0; half < 2; half++) {
            int m = r0 + half*8;
#pragma unroll
            for (int ni = 0; ni < 4; ni++) {
                int col = bn + wn*32 + ni*8 + (lane & 3)*2;
                float v0 = acc[mi][ni][half*2 + 0];
                float v1 = acc[mi][ni][half*2 + 1];
                if (bias) { v0 += bias[col]; v1 += bias[col + 1]; }
                if (act == ACT_RELU) { v0 = fmaxf(v0, 0.f); v1 = fmaxf(v1, 0.f); }
                else if (act == ACT_SP) {
                    v0 = (v0 > 20.f) ? v0 : log1pf(expf(v0));
                    v1 = (v1 > 20.f) ? v1 : log1pf(expf(v1));
                }
                if (Cf) {
                    float* dst = Cf + (size_t)m*ldc + col;
                    if (accum) { dst[0] += v0; dst[1] += v1; }
                    else       { *(float2*)dst = make_float2(v0, v1); }
                }
                if (Ct) {
                    __nv_bfloat16 h0 = __float2bfloat16(v0);
                    __nv_bfloat16 h1 = __float2bfloat16(v1);
                    __nv_bfloat16 l0 = __float2bfloat16(v0 - __bfloat162float(h0));
                    __nv_bfloat16 l1 = __float2bfloat16(v1 - __bfloat162float(h1));
                    __nv_bfloat16* d0 = Ct + (size_t)m*(3*(size_t)Kn) + col;
                    *(__nv_bfloat162*)(d0)        = __nv_bfloat162(h0, h1);
                    *(__nv_bfloat162*)(d0 + Kn)   = __nv_bfloat162(l0, l1);
                    *(__nv_bfloat162*)(d0 + 2*Kn) = __nv_bfloat162(h0, h1);
                }
            }
        }
    }
}

// ---------------- weight triple conversion (B-side: [hi|hi|lo]) ----------------
__global__ void triple_w_kernel(const float* __restrict__ src, __nv_bfloat16* __restrict__ dst,
                                int K, size_t total) {
    size_t idx = (size_t)blockIdx.x * blockDim.x + threadIdx.x;
    if (idx >= total) return;
    size_t r = idx / K, k = idx % K;
    float v = src[idx];
    __nv_bfloat16 hi = __float2bfloat16(v);
    __nv_bfloat16 lo = __float2bfloat16(v - __bfloat162float(hi));
    __nv_bfloat16* d = dst + r*(size_t)(3*K) + k;
    d[0] = hi; d[K] = hi; d[2*K] = lo;
}

// ---------------- RMSNorm -> triple bf16 (A-side: [hi|lo|hi]) ----------------
__global__ void rmsnorm_kernel(const float* __restrict__ h, const float* __restrict__ w,
                               __nv_bfloat16* __restrict__ out3) {
    int row = blockIdx.x;
    const float* hr = h + (size_t)row * DM_;
    float v[4];
    float s = 0.f;
#pragma unroll
    for (int i = 0; i < 4; i++) { v[i] = hr[threadIdx.x + i*256]; s += v[i]*v[i]; }
    __shared__ float sh[8];
    int lane = threadIdx.x & 31, wp = threadIdx.x >> 5;
#pragma unroll
    for (int o = 16; o; o >>= 1) s += __shfl_xor_sync(0xffffffffu, s, o);
    if (lane == 0) sh[wp] = s;
    __syncthreads();
    if (wp == 0) {
        float t = (lane < 8) ? sh[lane] : 0.f;
#pragma unroll
        for (int o = 4; o; o >>= 1) t += __shfl_xor_sync(0xffffffffu, t, o);
        if (lane == 0) sh[0] = t;
    }
    __syncthreads();
    float rs = rsqrtf(sh[0] * (1.f/DM_) + 1e-5f);
    __nv_bfloat16* orow = out3 + (size_t)row * (3*DM_);
#pragma unroll
    for (int i = 0; i < 4; i++) {
        int d = threadIdx.x + i*256;
        float val = v[i]*rs*w[d];
        __nv_bfloat16 hi = __float2bfloat16(val);
        __nv_bfloat16 lo = __float2bfloat16(val - __bfloat162float(hi));
        orow[d] = hi; orow[DM_ + d] = lo; orow[2*DM_ + d] = hi;
    }
}

// ---------------- fp32 SGEMM (small shapes: dC, delta) ----------------
__global__ __launch_bounds__(256)
void sgemm_kernel(const float* __restrict__ A, const float* __restrict__ Bm,
                  float* __restrict__ C, const float* __restrict__ bias,
                  int M, int N, int K, int lda, int ldb, int ldc,
                  int act, int accum) {
    __shared__ float As[16][132];
    __shared__ float Bs[16][132];
    int tid = threadIdx.x;
    int bm = blockIdx.y * 128, bn = blockIdx.x * 128;
    int tx = tid & 15, ty = tid >> 4;
    float acc[8][8];
#pragma unroll
    for (int i = 0; i < 8; i++)
#pragma unroll
        for (int j = 0; j < 8; j++) acc[i][j] = 0.f;
    for (int k0 = 0; k0 < K; k0 += 16) {
#pragma unroll
        for (int i = 0; i < 8; i++) {
            int idx = tid + i*256;
            int r = idx >> 4, c2 = idx & 15;
            int gk = k0 + c2;
            int gm = bm + r;
            As[c2][r] = (gm < M && gk < K) ? A[(size_t)gm*lda + gk] : 0.f;
            int gn = bn + r;
            Bs[c2][r] = (gn < N && gk < K) ? Bm[(size_t)gn*ldb + gk] : 0.f;
        }
        __syncthreads();
#pragma unroll
        for (int kk = 0; kk < 16; kk++) {
            float a[8], b[8];
#pragma unroll
            for (int i = 0; i < 8; i++) a[i] = As[kk][ty*8 + i];
#pragma unroll
            for (int j = 0; j < 8; j++) b[j] = Bs[kk][tx*8 + j];
#pragma unroll
            for (int i = 0; i < 8; i++)
#pragma unroll
                for (int j = 0; j < 8; j++) acc[i][j] += a[i]*b[j];
        }
        __syncthreads();
    }
#pragma unroll
    for (int i = 0; i < 8; i++) {
        int row = bm + ty*8 + i;
        if (row >= M) continue;
#pragma unroll
        for (int j = 0; j < 8; j++) {
            int col = bn + tx*8 + j;
            if (col >= N) continue;
            float v = acc[i][j];
            if (bias) v += bias[col];
            if (act == ACT_RELU)      v = fmaxf(v, 0.f);
            else if (act == ACT_SP)   v = (v > 20.f) ? v : log1pf(expf(v));
            size_t o = (size_t)row*ldc + col;
            if (accum) C[o] += v; else C[o] = v;
        }
    }
}

// ---------------- fused 2x depthwise conv (k=2, causal) + SiLU ----------------
__global__ void conv_silu_kernel(const float* __restrict__ xz,
                                 const float* __restrict__ c1w, const float* __restrict__ c1b,
                                 const float* __restrict__ c2w, const float* __restrict__ c2b,
                                 float* __restrict__ out) {
    size_t idx = (size_t)blockIdx.x * blockDim.x + threadIdx.x;
    if (idx >= (size_t)BL_*ED_) return;
    int e = (int)(idx % ED_);
    size_t bl = idx / ED_;
    int l = (int)(bl % L_);
    size_t base = bl * (size_t)(2*ED_) + e;
    float x2 = xz[base];
    float x1 = (l >= 1) ? xz[base - 2*ED_] : 0.f;
    float x0 = (l >= 2) ? xz[base - 4*ED_] : 0.f;
    float w10 = c1w[e*2], w11 = c1w[e*2+1], b1 = c1b[e];
    float w20 = c2w[e*2], w21 = c2w[e*2+1], b2 = c2b[e];
    float y1b = b1 + w10*x1 + w11*x2;
    float y1a = (l >= 1) ? (b1 + w10*x0 + w11*x1) : 0.f;
    float y2 = b2 + w20*y1a + w21*y1b;
    out[idx] = siluf(y2);
}

// ---------------- Kerr = softsign((xg - y_prev)^2) -> triple bf16 ----------------
__global__ void kerr_kernel(const float* __restrict__ xs, const float* __restrict__ y,
                            __nv_bfloat16* __restrict__ kerr3, int s0, int useY) {
    size_t idx = (size_t)blockIdx.x * blockDim.x + threadIdx.x;
    if (idx >= (size_t)MSEG_*ED_) return;
    int e = (int)(idx % ED_);
    int row = (int)(idx / ED_);
    int b = row / SEG_, t = row % SEG_;
    size_t xi = ((size_t)(b*L_ + s0 + t))*ED_ + e;
    float xv = xs[xi];
    float yv = useY ? y[xi - (size_t)SEG_*ED_] : 0.f;
    float u = xv - yv; u = u*u;
    float val = u / (1.f + u);
    __nv_bfloat16 hi = __float2bfloat16(val);
    __nv_bfloat16 lo = __float2bfloat16(val - __bfloat162float(hi));
    __nv_bfloat16* d = kerr3 + (size_t)row*(3*ED_) + e;
    d[0] = hi; d[ED_] = lo; d[2*ED_] = hi;
}

// ---------------- LayerNorm(h3) + K EMA update ----------------
__global__ void ln_kupdate_kernel(const float* __restrict__ h3, const float* __restrict__ g,
                                  const float* __restrict__ bb, const float* __restrict__ kalpha,
                                  float* __restrict__ K) {
    int row = blockIdx.x;
    const float* hr = h3 + (size_t)row * ED_;
    float v[8];
    float s = 0.f;
#pragma unroll
    for (int i = 0; i < 8; i++) { v[i] = hr[threadIdx.x + i*256]; s += v[i]; }
    __shared__ float sh[8];
    __shared__ float mu_s, rs_s;
    int lane = threadIdx.x & 31, wp = threadIdx.x >> 5;
#pragma unroll
    for (int o = 16; o; o >>= 1) s += __shfl_xor_sync(0xffffffffu, s, o);
    if (lane == 0) sh[wp] = s;
    __syncthreads();
    if (threadIdx.x == 0) {
        float t = 0.f;
#pragma unroll
        for (int i = 0; i < 8; i++) t += sh[i];
        mu_s = t * (1.f/ED_);
    }
    __syncthreads();
    float mu = mu_s;
    float s2 = 0.f;
#pragma unroll
    for (int i = 0; i < 8; i++) { float d = v[i] - mu; s2 += d*d; }
#pragma unroll
    for (int o = 16; o; o >>= 1) s2 += __shfl_xor_sync(0xffffffffu, s2, o);
    if (lane == 0) sh[wp] = s2;
    __syncthreads();
    if (threadIdx.x == 0) {
        float t = 0.f;
#pragma unroll
        for (int i = 0; i < 8; i++) t += sh[i];
        rs_s = rsqrtf(t * (1.f/ED_) + 1e-5f);
    }
    __syncthreads();
    float rs = rs_s;
#pragma unroll
    for (int i = 0; i < 8; i++) {
        int e = threadIdx.x + i*256;
        float a = fminf(fmaxf(kalpha[e], 0.01f), 0.99f);
        float kn = g[e]*(v[i] - mu)*rs + bb[e];
        size_t ki = (size_t)row*ED_ + e;
        K[ki] = (1.f - a)*K[ki] + a*kn;
    }
}

// ---------------- DFT forward ----------------
__global__ void dft_fwd_kernel(const float* __restrict__ xs, float* __restrict__ Xr,
                               float* __restrict__ Xi, int s0) {
    int blk = blockIdx.x;
    int b = blk / (ED_/4);
    int e0 = (blk % (ED_/4)) * 4;
    __shared__ float xsh[4][SEG_+4];
    __shared__ float ct[SEG_], st[SEG_];
    int t = threadIdx.x;
    {
        float ang = 6.283185307179586f * (float)t / (float)SEG_;
        ct[t] = cosf(ang); st[t] = sinf(ang);
    }
#pragma unroll
    for (int j = 0; j < 4; j++) {
        int idx = t + j*256;
        int q = idx & 3, tt = idx >> 2;
        xsh[q][tt] = xs[((size_t)(b*L_ + s0 + tt))*ED_ + e0 + q];
    }
    __syncthreads();
    float ar[4] = {0,0,0,0}, ai[4] = {0,0,0,0};
    int k = t;
    for (int tt = 0; tt < SEG_; tt++) {
        int p = (k*tt) & (SEG_-1);
        float c = ct[p], s = st[p];
#pragma unroll
        for (int q = 0; q < 4; q++) { float xv = xsh[q][tt]; ar[q] += xv*c; ai[q] -= xv*s; }
    }
#pragma unroll
    for (int q = 0; q < 4; q++) {
        size_t o = ((size_t)(b*ED_ + e0 + q))*SEG_ + k;
        Xr[o] = ar[q]; Xi[o] = ai[q];
    }
}

// ---------------- inverse DFT of i*omega*g*X, Kdy = K * real(ifft) ----------------
__global__ void dft_inv_kernel(const float* __restrict__ Xr, const float* __restrict__ Xi,
                               const float* __restrict__ delta, const float* __restrict__ Kbuf,
                               const float* __restrict__ sigp, float* __restrict__ Kdy, int s0) {
    int blk = blockIdx.x;
    int b = blk / (ED_/4);
    int e0 = (blk % (ED_/4)) * 4;
    float sig = *sigp;
    __shared__ float Yr[4][SEG_+4], Yi[4][SEG_+4];
    __shared__ float ct[SEG_], st[SEG_];
    int t = threadIdx.x;
    {
        float ang = 6.283185307179586f * (float)t / (float)SEG_;
        ct[t] = cosf(ang); st[t] = sinf(ang);
    }
    {
        int k = t;
        float f = (k < SEG_/2) ? (float)k/(float)SEG_ : (float)(k - SEG_)/(float)SEG_;
        float g = expf(-f*f*sig*sig);
        float wbase = 6.283185307179586f * f;
#pragma unroll
        for (int q = 0; q < 4; q++) {
            float dt = delta[((size_t)(b*L_ + s0 + k))*ED_ + e0 + q];
            float w = wbase / (dt + 1e-5f);
            size_t o = ((size_t)(b*ED_ + e0 + q))*SEG_ + k;
            float xr = Xr[o], xi = Xi[o];
            Yr[q][k] = -w*g*xi;
            Yi[q][k] =  w*g*xr;
        }
    }
    __syncthreads();
    float acc[4] = {0,0,0,0};
    for (int k = 0; k < SEG_; k++) {
        int p = (k*t) & (SEG_-1);
        float c = ct[p], s = st[p];
#pragma unroll
        for (int q = 0; q < 4; q++) acc[q] += Yr[q][k]*c - Yi[q][k]*s;
    }
#pragma unroll
    for (int q = 0; q < 4; q++) {
        size_t oi = ((size_t)(b*SEG_ + t))*ED_ + e0 + q;
        Kdy[oi] = Kbuf[oi] * acc[q] * (1.f/(float)SEG_);
    }
}

// ---------------- segment scan: chunked two-pass, writes y directly ----------------
__global__ void scan_kernel(const float* __restrict__ xs, const float* __restrict__ delta,
                            const float* __restrict__ Kbuf, const float* __restrict__ Kdy,
                            const float* __restrict__ dC, const float* __restrict__ Alog,
                            const float* __restrict__ Dp, float* __restrict__ y, int s0) {
    int b = blockIdx.y;
    int lane = threadIdx.x & 31;
    int chunk = threadIdx.x >> 5;
    int e = blockIdx.x*32 + lane;
    __shared__ float C0s[SEG_], C1s[SEG_];
    __shared__ float sA0[8][33], sB0[8][33], sA1[8][33], sB1[8][33];
    __shared__ float pB0[8][33], pB1[8][33];
    {
        int t = threadIdx.x;
        size_t ci = ((size_t)(b*L_ + s0 + t))*DCN_ + DTR_;
        C0s[t] = dC[ci];
        C1s[t] = dC[ci + 1];
    }
    float A0v = -expf(Alog[e*2]);
    float A1v = -expf(Alog[e*2 + 1]);
    float Dpe = Dp[e];
    __syncthreads();

    float Ag0 = 1.f, Bg0 = 0.f, Ag1 = 1.f, Bg1 = 0.f;
    int tbase = chunk*32;
    for (int j = 0; j < 32; j++) {
        int t = tbase + j;
        size_t xi = ((size_t)(b*L_ + s0 + t))*ED_ + e;
        size_t ki = ((size_t)(b*SEG_ + t))*ED_ + e;
        float x = xs[xi], dg = delta[xi], Kv = Kbuf[ki], kd = Kdy[ki];
        float C0 = C0s[t], C1 = C1s[t];
        float KC0 = Kv*C0, AmK0 = A0v*(1.f - KC0);
        float a0 = expf(dg*AmK0*(1.f + KC0));
        float b0 = -dg*AmK0*Kv*x + kd;
        Bg0 = a0*Bg0 + b0; Ag0 *= a0;
        float KC1 = Kv*C1, AmK1 = A1v*(1.f - KC1);
        float a1 = expf(dg*AmK1*(1.f + KC1));
        float b1 = -dg*AmK1*Kv*x + kd;
        Bg1 = a1*Bg1 + b1; Ag1 *= a1;
    }
    sA0[chunk][lane] = Ag0; sB0[chunk][lane] = Bg0;
    sA1[chunk][lane] = Ag1; sB1[chunk][lane] = Bg1;
    __syncthreads();

    if (threadIdx.x < 64) {
        int s = threadIdx.x >> 5, ln = threadIdx.x & 31;
        float pb = 0.f;
        if (s == 0) {
#pragma unroll
            for (int c = 0; c < 8; c++) { pB0[c][ln] = pb; pb = sA0[c][ln]*pb + sB0[c][ln]; }
        } else {
#pragma unroll
            for (int c = 0; c < 8; c++) { pB1[c][ln] = pb; pb = sA1[c][ln]*pb + sB1[c][ln]; }
        }
    }
    __syncthreads();

    float h0 = pB0[chunk][lane], h1 = pB1[chunk][lane];
    for (int j = 0; j < 32; j++) {
        int t = tbase + j;
        size_t xi = ((size_t)(b*L_ + s0 + t))*ED_ + e;
        size_t ki = ((size_t)(b*SEG_ + t))*ED_ + e;
        float x = xs[xi], dg = delta[xi], Kv = Kbuf[ki], kd = Kdy[ki];
        float C0 = C0s[t], C1 = C1s[t];
        float KC0 = Kv*C0, AmK0 = A0v*(1.f - KC0);
        float a0 = expf(dg*AmK0*(1.f + KC0));
        float b0 = -dg*AmK0*Kv*x + kd;
        h0 = a0*h0 + b0;
        float KC1 = Kv*C1, AmK1 = A1v*(1.f - KC1);
        float a1 = expf(dg*AmK1*(1.f + KC1));
        float b1 = -dg*AmK1*Kv*x + kd;
        h1 = a1*h1 + b1;
        y[xi] = h0*C0 + h1*C1 + Dpe*x;
    }
}

// ---------------- gate: gated3 = triple_bf16(y * silu(z)) ----------------
__global__ void gate_kernel(const float* __restrict__ y, const float* __restrict__ xz,
                            __nv_bfloat16* __restrict__ gt3) {
    size_t idx = (size_t)blockIdx.x * blockDim.x + threadIdx.x;
    if (idx >= (size_t)BL_*ED_) return;
    int e = (int)(idx % ED_);
    size_t bl = idx / ED_;
    float z = xz[bl*(size_t)(2*ED_) + ED_ + e];
    float val = y[idx] * siluf(z);
    __nv_bfloat16 hi = __float2bfloat16(val);
    __nv_bfloat16 lo = __float2bfloat16(val - __bfloat162float(hi));
    __nv_bfloat16* d = gt3 + bl*(size_t)(3*ED_) + e;
    d[0] = hi; d[ED_] = lo; d[2*ED_] = hi;
}

// ---------------- host orchestration ----------------
extern "C" void kernel_launch(void* const* d_in, const int* in_sizes, int n_in,
                              void* d_out, int out_size) {
    const float* x      = (const float*)d_in[0];
    const float* rms_w  = (const float*)d_in[1];
    const float* in_w   = (const float*)d_in[2];
    const float* c1_w   = (const float*)d_in[3];
    const float* c1_b   = (const float*)d_in[4];
    const float* c2_w   = (const float*)d_in[5];
    const float* c2_b   = (const float*)d_in[6];
    const float* xp_w   = (const float*)d_in[7];
    const float* dt_w   = (const float*)d_in[8];
    const float* dt_b   = (const float*)d_in[9];
    const float* A_log  = (const float*)d_in[10];
    const float* Dp     = (const float*)d_in[11];
    const float* out_w  = (const float*)d_in[12];
    const float* k1_w   = (const float*)d_in[13];
    const float* k1_b   = (const float*)d_in[14];
    const float* k2_w   = (const float*)d_in[15];
    const float* k3_w   = (const float*)d_in[16];
    const float* ln_g   = (const float*)d_in[17];
    const float* ln_b   = (const float*)d_in[18];
    const float* kalpha = (const float*)d_in[19];
    const float* sigma  = (const float*)d_in[20];

    float* h = (float*)d_out;

    float *xz, *xs, *delta, *dC, *y, *K, *h3, *Xr, *Xi, *Kdy;
    __nv_bfloat16 *xn3, *inw3, *kerr3, *k1w3, *h13, *k2w3, *h23, *k3w3, *gt3, *outw3;
    cudaGetSymbolAddress((void**)&xz,    g_xz);
    cudaGetSymbolAddress((void**)&xs,    g_xs);
    cudaGetSymbolAddress((void**)&delta, g_delta);
    cudaGetSymbolAddress((void**)&dC,    g_dC);
    cudaGetSymbolAddress((void**)&y,     g_y);
    cudaGetSymbolAddress((void**)&K,     g_K);
    cudaGetSymbolAddress((void**)&h3,    g_h3);
    cudaGetSymbolAddress((void**)&Xr,    g_Xr);
    cudaGetSymbolAddress((void**)&Xi,    g_Xi);
    cudaGetSymbolAddress((void**)&Kdy,   g_Kdy);
    cudaGetSymbolAddress((void**)&xn3,   g_xn3);
    cudaGetSymbolAddress((void**)&inw3,  g_inw3);
    cudaGetSymbolAddress((void**)&kerr3, g_kerr3);
    cudaGetSymbolAddress((void**)&k1w3,  g_k1w3);
    cudaGetSymbolAddress((void**)&h13,   g_h13);
    cudaGetSymbolAddress((void**)&k2w3,  g_k2w3);
    cudaGetSymbolAddress((void**)&h23,   g_h23);
    cudaGetSymbolAddress((void**)&k3w3,  g_k3w3);
    cudaGetSymbolAddress((void**)&gt3,   g_gt3);
    cudaGetSymbolAddress((void**)&outw3, g_outw3);

    cudaFuncSetAttribute(tcgemm_kernel, cudaFuncAttributeMaxDynamicSharedMemorySize, TCG_SMEM);

    // h = x (residual stream lives in d_out)
    cudaMemcpyAsync(h, x, sizeof(float)*(size_t)BL_*DM_, cudaMemcpyDeviceToDevice);

    const int EL_BLOCKS = (int)(((size_t)BL_*ED_ + 255) / 256);
    const int KE_BLOCKS = (int)(((size_t)MSEG_*ED_ + 255) / 256);

    for (int i = 0; i < NL_; i++) {
        const float* rw   = rms_w + (size_t)i*DM_;
        const float* iw   = in_w  + (size_t)i*2*ED_*DM_;
        const float* c1wi = c1_w  + (size_t)i*ED_*2;
        const float* c1bi = c1_b  + (size_t)i*ED_;
        const float* c2wi = c2_w  + (size_t)i*ED_*2;
        const float* c2bi = c2_b  + (size_t)i*ED_;
        const float* xpwi = xp_w  + (size_t)i*DCN_*ED_;
        const float* dtwi = dt_w  + (size_t)i*ED_*DTR_;
        const float* dtbi = dt_b  + (size_t)i*ED_;
        const float* Ali  = A_log + (size_t)i*ED_*N_;
        const float* Dpi  = Dp    + (size_t)i*ED_;
        const float* owi  = out_w + (size_t)i*DM_*ED_;
        const float* k1wi = k1_w  + (size_t)i*T3_*ED_;
        const float* k1bi = k1_b  + (size_t)i*T3_;
        const float* k2wi = k2_w  + (size_t)i*ED_*T3_;
        const float* k3wi = k3_w  + (size_t)i*ED_*ED_;
        const float* lngi = ln_g  + (size_t)i*ED_;
        const float* lnbi = ln_b  + (size_t)i*ED_;
        const float* kai  = kalpha+ (size_t)i*ED_;
        const float* sigi = sigma + i;

        // weight conversions (B-side triple)
        {
            size_t t1 = (size_t)2*ED_*DM_;
            triple_w_kernel<<<(int)((t1+255)/256), 256>>>(iw, inw3, DM_, t1);
            size_t t2 = (size_t)T3_*ED_;
            triple_w_kernel<<<(int)((t2+255)/256), 256>>>(k1wi, k1w3, ED_, t2);
            size_t t3 = (size_t)ED_*T3_;
            triple_w_kernel<<<(int)((t3+255)/256), 256>>>(k2wi, k2w3, T3_, t3);
            size_t t4 = (size_t)ED_*ED_;
            triple_w_kernel<<<(int)((t4+255)/256), 256>>>(k3wi, k3w3, ED_, t4);
            size_t t5 = (size_t)DM_*ED_;
            triple_w_kernel<<<(int)((t5+255)/256), 256>>>(owi, outw3, ED_, t5);
        }

        // RMSNorm -> xn3 (A-side triple)
        rmsnorm_kernel<<<BL_, 256>>>(h, rw, xn3);
        // in-proj: xz = xn @ in_w^T   (8192 x 4096, K3=3072)
        tcgemm_kernel<<<dim3(2*ED_/128, BL_/128), 256, TCG_SMEM>>>(
            xn3, inw3, xz, nullptr, nullptr, 3*DM_, 2*ED_, 0, ACT_NONE, 0);
        // fused conv1 -> conv2 -> silu
        conv_silu_kernel<<<EL_BLOCKS, 256>>>(xz, c1wi, c1bi, c2wi, c2bi, xs);
        // dC = xs @ xp_w^T (N=66)
        sgemm_kernel<<<dim3((DCN_+127)/128, BL_/128), 256>>>(
            xs, xpwi, dC, nullptr, BL_, DCN_, ED_, ED_, ED_, DCN_, ACT_NONE, 0);
        // delta = softplus(dr @ dt_w^T + dt_b)
        sgemm_kernel<<<dim3(ED_/128, BL_/128), 256>>>(
            dC, dtwi, delta, dtbi, BL_, ED_, DTR_, DCN_, DTR_, ED_, ACT_SP, 0);

        cudaMemsetAsync(K, 0, sizeof(float)*(size_t)MSEG_*ED_);

        for (int s = 0; s < NSEG_; s++) {
            int s0 = s * SEG_;
            kerr_kernel<<<KE_BLOCKS, 256>>>(xs, y, kerr3, s0, s > 0);
            // h1 = relu(Kerr @ k1_w^T + k1_b) -> triple (1024 x 6144, K3=6144)
            tcgemm_kernel<<<dim3(T3_/128, MSEG_/128), 256, TCG_SMEM>>>(
                kerr3, k1w3, nullptr, h13, k1bi, 3*ED_, 0, T3_, ACT_RELU, 0);
            // h2 = relu(h1 @ k2_w^T) -> triple (1024 x 2048, K3=18432)
            tcgemm_kernel<<<dim3(ED_/128, MSEG_/128), 256, TCG_SMEM>>>(
                h13, k2w3, nullptr, h23, nullptr, 3*T3_, 0, ED_, ACT_RELU, 0);
            // h3 = h2 @ k3_w^T -> fp32 (1024 x 2048, K3=6144)
            tcgemm_kernel<<<dim3(ED_/128, MSEG_/128), 256, TCG_SMEM>>>(
                h23, k3w3, h3, nullptr, nullptr, 3*ED_, ED_, 0, ACT_NONE, 0);
            // K = (1-a)K + a*LN(h3)
            ln_kupdate_kernel<<<MSEG_, 256>>>(h3, lngi, lnbi, kai, K);
            // FFT derivative unit
            dft_fwd_kernel<<<B_*ED_/4, 256>>>(xs, Xr, Xi, s0);
            dft_inv_kernel<<<B_*ED_/4, 256>>>(Xr, Xi, delta, K, sigi, Kdy, s0);
            // scan -> y segment
            scan_kernel<<<dim3(ED_/32, B_), 256>>>(xs, delta, K, Kdy, dC, Ali, Dpi, y, s0);
        }

        // gated3 = triple(y * silu(z))
        gate_kernel<<<EL_BLOCKS, 256>>>(y, xz, gt3);
        // h += gated @ out_w^T  (8192 x 1024, K3=6144)
        tcgemm_kernel<<<dim3(DM_/128, BL_/128), 256, TCG_SMEM>>>(
            gt3, outw3, h, nullptr, nullptr, 3*ED_, DM_, 0, ACT_NONE, 1);
    }
}